// round 17
// baseline (speedup 1.0000x reference)
#include <cuda_runtime.h>
#include <cuda_fp16.h>
#include <mma.h>
#include <cstdint>

using namespace nvcuda;

// Problem constants
#define B_      128
#define CIN     128
#define LEGO_   128
#define OUTC    512
#define HW      1024
#define W_IMG   32
#define NLAB    10
#define NTAPS   9
#define KCHUNK  64
#define NCHUNKS 18            // 9 taps * 2 ic-blocks  (k = tap*128 + ic)
#define NTILE   128           // pixels per CTA (4 image rows)
#define NSTAGE  3
#define LDA_K   72            // A smem ld (halfs): 144B rows (64 + 8 pad)
#define LDB_N   136           // B smem ld (halfs): 272B rows (128 + 8 pad)
#define LDF     132           // feat smem ld (floats)

#define A_STAGE_BYTES (128 * LDA_K * 2)     // 18432
#define B_STAGE_BYTES (KCHUNK * LDB_N * 2)  // 17408
#define STAGE_BYTES   (A_STAGE_BYTES + B_STAGE_BYTES)   // 35840
#define DSM_BYTES     (NSTAGE * STAGE_BYTES)            // 107520 (> feat 67584)

__device__ int   g_sel[OUTC];
__device__ float g_scale[OUTC];
__device__ __align__(16) __half g_wA[NLAB * LEGO_ * NTAPS * CIN];  // [lab][m][tap][ic]
__device__ __align__(16) __half g_xsh[3][B_][CIN][W_IMG][W_IMG];   // [dw][b][ic][r][c]

__device__ __forceinline__ uint32_t smem_u32(const void* p) {
    uint32_t a;
    asm("{ .reg .u64 t; cvta.to.shared.u64 t, %1; cvt.u32.u64 %0, t; }"
        : "=r"(a) : "l"(p));
    return a;
}
__device__ __forceinline__ void cp16(uint32_t dst, const void* src, int srcsize) {
    asm volatile("cp.async.cg.shared.global [%0], [%1], 16, %2;"
                 :: "r"(dst), "l"(__cvta_generic_to_global(src)), "r"(srcsize)
                 : "memory");
}
#define CP_COMMIT() asm volatile("cp.async.commit_group;" ::: "memory")
#define CP_WAIT1()  asm volatile("cp.async.wait_group 1;" ::: "memory")

// ---------------------------------------------------------------------------
// Kernel 1: forward select map, warp-per-o (argmax = first max, strict >).
// ---------------------------------------------------------------------------
__global__ void select_kernel(const float* __restrict__ coeff,
                              const float* __restrict__ comb) {
    const int wid = threadIdx.x >> 5;
    const int lid = threadIdx.x & 31;
    const int o   = blockIdx.x * 16 + wid;

    const float* row = comb + o * LEGO_;
    float4 v = *reinterpret_cast<const float4*>(row + lid * 4);
    float m  = v.x; int mi = lid * 4;
    if (v.y > m) { m = v.y; mi = lid * 4 + 1; }
    if (v.z > m) { m = v.z; mi = lid * 4 + 2; }
    if (v.w > m) { m = v.w; mi = lid * 4 + 3; }
    #pragma unroll
    for (int off = 16; off > 0; off >>= 1) {
        float m2 = __shfl_down_sync(0xFFFFFFFF, m, off);
        int  mi2 = __shfl_down_sync(0xFFFFFFFF, mi, off);
        if (m2 > m || (m2 == m && mi2 < mi)) { m = m2; mi = mi2; }
    }
    if (lid == 0) {
        g_sel[o]   = mi;
        g_scale[o] = coeff[o * LEGO_ + mi];
    }
}

// ---------------------------------------------------------------------------
// Kernel 2: weight transpose+convert via smem, block per (lab, m).
// ---------------------------------------------------------------------------
__global__ void prep_w_kernel(const float* __restrict__ ff) {
    __shared__ float s[NTAPS * CIN];         // 1152
    const int bm  = blockIdx.x;              // lab*128 + m
    const int t   = threadIdx.x;             // 0..127
    const float* src = ff + (size_t)bm * NTAPS * CIN;
    #pragma unroll
    for (int j = 0; j < 9; j++) s[t + j * 128] = src[t + j * 128];
    __syncthreads();
    __half* dst = g_wA + (size_t)bm * NTAPS * CIN;
    #pragma unroll
    for (int j = 0; j < 9; j++) {
        int e   = t + j * 128;               // = tap*128 + ic
        int tap = e >> 7, ic = e & 127;
        dst[e] = __float2half_rn(s[ic * 9 + tap]);
    }
}

// ---------------------------------------------------------------------------
// Kernel 3: 3 column-shifted fp16 copies of x.
// ---------------------------------------------------------------------------
__global__ void prep_x_kernel(const float* __restrict__ x) {
    int idx = blockIdx.x * 256 + threadIdx.x;       // over 128*128*32
    if (idx >= B_ * CIN * W_IMG) return;
    const float* src = x + (size_t)idx * W_IMG;
    float v[32];
    #pragma unroll
    for (int j = 0; j < 8; j++) {
        float4 f = *reinterpret_cast<const float4*>(src + j * 4);
        v[j * 4] = f.x; v[j * 4 + 1] = f.y; v[j * 4 + 2] = f.z; v[j * 4 + 3] = f.w;
    }
    #pragma unroll
    for (int dw = 0; dw < 3; dw++) {
        __half h[32];
        #pragma unroll
        for (int c = 0; c < 32; c++) {
            int s = c + dw - 1;
            h[c] = __float2half_rn((s >= 0 && s < 32) ? v[s] : 0.0f);
        }
        uint4* dst = reinterpret_cast<uint4*>(
            &g_xsh[dw][0][0][0][0] + (size_t)idx * W_IMG);
        #pragma unroll
        for (int j = 0; j < 4; j++)
            dst[j] = reinterpret_cast<const uint4*>(h)[j];
    }
}

// ---------------------------------------------------------------------------
// Kernel 4: fp16 wmma GEMM conv, 8 warps (32x64 tiles), KCHUNK=64, cp.async
// 3-stage ring (wait_group 1, distance-2 prefetch), 2 CTAs/SM, fused scatter.
// grid = (8 tiles, 128 batches), 256 threads.
// ---------------------------------------------------------------------------
__global__ __launch_bounds__(256, 2)
void conv_wmma_kernel(const int* __restrict__ label,
                      float*     __restrict__ out) {
    extern __shared__ char dsm[];

    const int tid  = threadIdx.x;
    const int wid  = tid >> 5;       // 0..7
    const int lid  = tid & 31;
    const int tile = blockIdx.x;     // 0..7
    const int b    = blockIdx.y;     // 0..127
    const int pix0 = tile * NTILE;
    const int lab  = label[b];

    // fill roles (256 threads)
    const int am  = tid >> 1, ah = tid & 1;   // A: row m, 32-half half (4 cp16)
    const int bk  = tid >> 2;                 // B: k-row (0..63)
    const int bs  = tid & 3;                  // B: image row in tile (4 cp16)

    // warp tile: 32 M x 64 N (warps: 4 in M x 2 in N)
    const int mrow = (wid & 3) * 32;
    const int ncol = (wid >> 2) * 64;

    uint32_t stA[NSTAGE]; half* stAp[NSTAGE]; half* stBp[NSTAGE];
    #pragma unroll
    for (int s = 0; s < NSTAGE; s++) {
        stA[s]  = smem_u32(dsm + s * STAGE_BYTES);
        stAp[s] = reinterpret_cast<half*>(dsm + s * STAGE_BYTES);
        stBp[s] = reinterpret_cast<half*>(dsm + s * STAGE_BYTES + A_STAGE_BYTES);
    }

    wmma::fragment<wmma::accumulator, 16, 16, 16, float> acc[2][4];
    #pragma unroll
    for (int mi = 0; mi < 2; mi++)
        #pragma unroll
        for (int ni = 0; ni < 4; ni++) wmma::fill_fragment(acc[mi][ni], 0.0f);

    auto fill = [&](int s, int chunk) {
        const int tap = chunk >> 1;             // 0..8
        const int ic0 = (chunk & 1) * KCHUNK;   // 0 or 64
        const int dh  = tap / 3;
        const int dw  = tap - dh * 3;
        // A: 32 halfs per thread (4 cp16)
        const __half* srcA = &g_wA[(((size_t)lab * LEGO_ + am) * NTAPS + tap) * CIN
                                   + ic0 + ah * 32];
        uint32_t dA = stA[s] + (am * LDA_K + ah * 32) * 2;
        #pragma unroll
        for (int j = 0; j < 4; j++)
            cp16(dA + j * 16, srcA + j * 8, 16);
        // B: one image row (32 px) for k-row bk: 4 cp16
        const int gr = tile * 4 + bs + dh - 1;
        const int ok = ((unsigned)gr < 32u) ? 16 : 0;
        const __half* srcB = &g_xsh[dw][b][ic0 + bk][gr & 31][0];
        uint32_t dB = stA[s] + A_STAGE_BYTES + (bk * LDB_N + bs * 32) * 2;
        #pragma unroll
        for (int j = 0; j < 4; j++)
            cp16(dB + j * 16, srcB + j * 8, ok);
    };

    // prologue: 2 fills in flight
    fill(0, 0); CP_COMMIT();
    fill(1, 1); CP_COMMIT();

    for (int chunk = 0; chunk < NCHUNKS; chunk++) {
        const int s = chunk % NSTAGE;
        CP_WAIT1();          // fill(chunk) landed (fill(chunk+1) may still fly)
        __syncthreads();     // stage s visible; compute(chunk-1) done in all warps
        if (chunk + 2 < NCHUNKS) fill((chunk + 2) % NSTAGE, chunk + 2);
        CP_COMMIT();         // empty group near tail keeps accounting invariant

        #pragma unroll
        for (int ks = 0; ks < 4; ks++) {
            wmma::fragment<wmma::matrix_a, 16, 16, 16, half,
                           wmma::row_major> af[2];
            #pragma unroll
            for (int mi = 0; mi < 2; mi++)
                wmma::load_matrix_sync(af[mi],
                    stAp[s] + (mrow + mi * 16) * LDA_K + ks * 16, LDA_K);
            #pragma unroll
            for (int ni = 0; ni < 4; ni++) {
                wmma::fragment<wmma::matrix_b, 16, 16, 16, half,
                               wmma::row_major> bf;
                wmma::load_matrix_sync(bf,
                    stBp[s] + (ks * 16) * LDB_N + ncol + ni * 16, LDB_N);
                #pragma unroll
                for (int mi = 0; mi < 2; mi++)
                    wmma::mma_sync(acc[mi][ni], af[mi], bf, acc[mi][ni]);
            }
        }
    }

    __syncthreads();         // all compute done before overlaying feat
    float* feat = reinterpret_cast<float*>(dsm);
    #pragma unroll
    for (int mi = 0; mi < 2; mi++)
        #pragma unroll
        for (int ni = 0; ni < 4; ni++)
            wmma::store_matrix_sync(
                feat + (mrow + mi * 16) * LDF + ncol + ni * 16,
                acc[mi][ni], LDF, wmma::mem_row_major);
    __syncthreads();

    // ---- coalesced scatter: 128 px per output channel, float4 per lane ----
    float* outb = out + (size_t)b * OUTC * HW + pix0;
    for (int o = wid; o < OUTC; o += 8) {
        const int   sl = g_sel[o];
        const float sc = g_scale[o];
        float4 v = *reinterpret_cast<const float4*>(&feat[sl * LDF + lid * 4]);
        v.x *= sc; v.y *= sc; v.z *= sc; v.w *= sc;
        *reinterpret_cast<float4*>(outb + (size_t)o * HW + lid * 4) = v;
    }
}

// ---------------------------------------------------------------------------
extern "C" void kernel_launch(void* const* d_in, const int* in_sizes, int n_in,
                              void* d_out, int out_size) {
    const float* x     = (const float*)d_in[0];
    const int*   label = (const int*)  d_in[1];
    const float* ff    = (const float*)d_in[2];
    const float* coeff = (const float*)d_in[3];
    const float* comb  = (const float*)d_in[4];
    float*       out   = (float*)d_out;

    static bool attr_set = false;
    if (!attr_set) {
        cudaFuncSetAttribute(conv_wmma_kernel,
                             cudaFuncAttributeMaxDynamicSharedMemorySize,
                             DSM_BYTES);
        attr_set = true;
    }

    select_kernel<<<32, 512>>>(coeff, comb);
    prep_w_kernel<<<NLAB * LEGO_, 128>>>(ff);
    prep_x_kernel<<<(B_ * CIN * W_IMG + 255) / 256, 256>>>(x);

    dim3 grid(HW / NTILE, B_);   // (8, 128)
    conv_wmma_kernel<<<grid, 256, DSM_BYTES>>>(label, out);
}